// round 16
// baseline (speedup 1.0000x reference)
#include <cuda_runtime.h>
#include <cuda_bf16.h>
#include <cuda_fp16.h>
#include <math.h>
#include <stdint.h>

// Problem constants
#define S_ 2
#define B_ 2048
#define D_ 1024
#define H_ 2048
#define E_ 8
#define O_ 1024
#define T_ (S_*B_)        // 4096 tokens
#define P_ (T_*2)         // 8192 (token, k) pairs
#define MAXR 4096
#define OUT_OFF ((size_t)B_*O_)

// ---------------- scratch (device globals) ----------------
__device__ __align__(128) __half g_xh[(size_t)T_ * D_];
__device__ __align__(128) __half g_w1h[(size_t)E_ * H_ * D_];
__device__ __align__(128) __half g_w2h[(size_t)E_ * H_ * H_];
__device__ __align__(128) __half g_fwh[(size_t)O_ * H_];
__device__ __align__(128) __half g_Hh[(size_t)P_ * H_];
__device__ __align__(128) __half g_Yh[(size_t)P_ * H_];
__device__ __align__(128) __half g_ch[(size_t)B_ * H_];
__device__ __align__(128) float g_gate[P_];
__device__ __align__(128) int   g_list[E_ * MAXR];
__device__ int   g_cnt[E_];

__device__ __forceinline__ uint32_t smem_u32(const void* p) {
    uint32_t a;
    asm("{ .reg .u64 t; cvta.to.shared.u64 t, %1; cvt.u32.u64 %0, t; }" : "=r"(a) : "l"(p));
    return a;
}

#define LDSM4(r0, r1, r2, r3, addr) \
    asm volatile("ldmatrix.sync.aligned.m8n8.x4.shared.b16 {%0,%1,%2,%3}, [%4];" \
        : "=r"(r0), "=r"(r1), "=r"(r2), "=r"(r3) : "r"(addr))

#define MMA16816(d, a, b) \
    asm volatile("mma.sync.aligned.m16n8k16.row.col.f32.f16.f16.f32 " \
        "{%0,%1,%2,%3}, {%4,%5,%6,%7}, {%8,%9}, {%0,%1,%2,%3};" \
        : "+f"((d)[0]), "+f"((d)[1]), "+f"((d)[2]), "+f"((d)[3]) \
        : "r"((a)[0]), "r"((a)[1]), "r"((a)[2]), "r"((a)[3]), \
          "r"((b)[0]), "r"((b)[1]))

#define CPA16(dst, src, sz) \
    asm volatile("cp.async.cg.shared.global [%0], [%1], 16, %2;" \
        :: "r"(dst), "l"(src), "r"(sz) : "memory")
#define CPCOMMIT() asm volatile("cp.async.commit_group;" ::: "memory")
#define CPWAIT(n)  asm volatile("cp.async.wait_group %0;" :: "n"(n) : "memory")

// swizzled byte offset within an N-row x 32-col fp16 plane (64B rows, 4x16B chunks)
__device__ __forceinline__ int swoff(int r, int c) {
    return r * 64 + ((c ^ ((r >> 1) & 3)) << 4);
}

// ---------------- fused pack: xs|w1|w2|fw -> fp16 ----------------
#define XSF4 (T_*D_/4)      // 1048576
#define W1F4 (E_*H_*D_/4)   // 4194304
#define W2F4 (E_*H_*H_/4)   // 8388608
#define FWF4 (O_*H_/4)      // 524288
#define PACK_BLKS 3552

__device__ __forceinline__ void pack_loop(const float* __restrict__ s,
                                          __half* __restrict__ d,
                                          size_t n4, size_t i0, size_t stride) {
    for (size_t j = i0; j < n4; j += stride) {
        float4 v = reinterpret_cast<const float4*>(s)[j];
        __half2 a = __floats2half2_rn(v.x, v.y);
        __half2 b = __floats2half2_rn(v.z, v.w);
        uint2 o;
        o.x = *reinterpret_cast<uint32_t*>(&a);
        o.y = *reinterpret_cast<uint32_t*>(&b);
        reinterpret_cast<uint2*>(d)[j] = o;
    }
}

__global__ __launch_bounds__(256) void pack_all(
        const float* __restrict__ xs, const float* __restrict__ w1,
        const float* __restrict__ w2, const float* __restrict__ fw)
{
    size_t i0 = (size_t)blockIdx.x * 256 + threadIdx.x;
    size_t stride = (size_t)PACK_BLKS * 256;
    pack_loop(xs, g_xh,  XSF4, i0, stride);
    pack_loop(w1, g_w1h, W1F4, i0, stride);
    pack_loop(w2, g_w2h, W2F4, i0, stride);
    pack_loop(fw, g_fwh, FWF4, i0, stride);
}

// ---------------- gating: 256 blocks x 16 tokens ----------------
__global__ __launch_bounds__(256) void gating_kernel(
        const float* __restrict__ xs, const float* __restrict__ Wg,
        const float* __restrict__ bias, float* __restrict__ out)
{
    __shared__ __align__(16) float ws[E_][D_];
    int tid = threadIdx.x;
    for (int i = tid; i < E_*D_; i += 256) {
        int e = i >> 10, d = i & (D_-1);
        ws[e][d] = Wg[d*E_ + e];
    }
    __syncthreads();
    int warp = tid >> 5, lane = tid & 31;
    for (int tt = 0; tt < 2; ++tt) {
        int t = blockIdx.x * 16 + warp * 2 + tt;
        float acc[E_];
        #pragma unroll
        for (int e = 0; e < E_; ++e) acc[e] = 0.f;
        const float4* xrow = reinterpret_cast<const float4*>(xs + (size_t)t * D_);
        #pragma unroll
        for (int it = 0; it < D_/128; ++it) {
            float4 x = xrow[lane + it*32];
            #pragma unroll
            for (int e = 0; e < E_; ++e) {
                float4 w = reinterpret_cast<const float4*>(ws[e])[lane + it*32];
                acc[e] += x.x*w.x + x.y*w.y + x.z*w.z + x.w*w.w;
            }
        }
        #pragma unroll
        for (int off = 16; off > 0; off >>= 1) {
            #pragma unroll
            for (int e = 0; e < E_; ++e)
                acc[e] += __shfl_xor_sync(0xffffffffu, acc[e], off);
        }
        if (lane == 0) {
            float h[E_];
            #pragma unroll
            for (int e = 0; e < E_; ++e) h[e] = acc[e] + bias[e];
            float m1 = h[0]; int i1 = 0;
            #pragma unroll
            for (int e = 1; e < E_; ++e) if (h[e] > m1) { m1 = h[e]; i1 = e; }
            float m2 = -3.0e38f; int i2 = 0;
            #pragma unroll
            for (int e = 0; e < E_; ++e) if (e != i1 && h[e] > m2) { m2 = h[e]; i2 = e; }
            float pr[E_]; float den = 0.f;
            #pragma unroll
            for (int e = 0; e < E_; ++e) { pr[e] = expf(h[e] - m1); den += pr[e]; }
            float inv = 1.f / den;
            float* ep = out + OUT_OFF + (size_t)t * E_;
            #pragma unroll
            for (int e = 0; e < E_; ++e) ep[e] = pr[e] * inv;
            float l2 = expf(m2 - m1);
            float gd = 1.f + l2;
            g_gate[t*2]     = 1.f / gd;
            g_gate[t*2 + 1] = l2 / gd;
            int pos = atomicAdd(&g_cnt[i1], 1); g_list[i1*MAXR + pos] = t*2;
            pos     = atomicAdd(&g_cnt[i2], 1); g_list[i2*MAXR + pos] = t*2 + 1;
        }
    }
}

// ---- fp16 mma.sync GEMM: 256 threads, tile BMx128, BK=32, 6-stage,
//      sync every 2 stages (2-stage cp.async groups), 2 CTA/SM ----
// Warp grid: 4 (m) x 2 (n); warp tile (BM/4) x 64.
// MODE 0: final (A=g_ch, W=g_fwh, C=out,  K=2048, N=1024, BM=64)
// MODE 1: fc1   (A=g_xh by token, W=g_w1h, C=g_Hh fp16, K=1024, N=2048, relu, BM=128)
// MODE 2: fc2   (A=g_Hh by pair,  W=g_w2h, C=g_Yh fp16, K=2048, N=2048, *gate, BM=128)
#define NSTG 6

template<int MODE>
__global__ __launch_bounds__(256, 2) void mma_gemm(
        const float* __restrict__ biasF, float* __restrict__ Cout)
{
    constexpr int K    = (MODE == 1) ? 1024 : 2048;
    constexpr int NTOT = (MODE == 0) ? 1024 : 2048;
    constexpr int NC   = K / 32;              // even for all modes
    constexpr int BM   = (MODE == 0) ? 64 : 128;
    constexpr int TA   = BM / 64;
    constexpr int TPR  = 256 / BM;
    constexpr int CHT  = 4 / TPR;
    constexpr int ABYTES = BM * 64;
    constexpr int STG  = ABYTES + 128 * 64;

    const __half *Ah_g, *Wh_g;
    if (MODE == 0)      { Ah_g = g_ch;  Wh_g = g_fwh; }
    else if (MODE == 1) { Ah_g = g_xh;  Wh_g = g_w1h; }
    else                { Ah_g = g_Hh;  Wh_g = g_w2h; }

    int e = (MODE == 0) ? 0 : blockIdx.z;
    int cnt;
    const int* lst = nullptr;
    if (MODE == 0) cnt = B_;
    else { cnt = g_cnt[e]; lst = g_list + e * MAXR; }
    int row0 = blockIdx.y * BM;
    if (row0 >= cnt) return;
    int n0blk = blockIdx.x * 128;
    const __half* Wb = Wh_g + (size_t)e * NTOT * K;
    const float* bb = biasF + (size_t)e * ((MODE == 0) ? 0 : NTOT);

    extern __shared__ unsigned char sm[];
    uint32_t su = smem_u32(sm);

    int tid = threadIdx.x;
    int wid = tid >> 5, lane = tid & 31;
    int warp_m = wid >> 1;
    int warp_n = wid & 1;

    // ---- cp.async assignment ----
    int r_ld = tid / TPR;
    int c0   = (tid % TPR) * CHT;
    int gr_ld = row0 + r_ld;
    uint32_t aSz = (gr_ld < cnt) ? 16u : 0u;
    int aridx;
    if (MODE == 0) aridx = (gr_ld < cnt) ? gr_ld : 0;
    else {
        int p = (gr_ld < cnt) ? lst[gr_ld] : 0;
        aridx = (MODE == 1) ? (p >> 1) : p;
    }
    const __half* aP = Ah_g + (size_t)aridx * K;
    int sA[CHT];
    #pragma unroll
    for (int j = 0; j < CHT; ++j) sA[j] = swoff(r_ld, c0 + j);
    int rb = tid >> 1, cb = (tid & 1) * 2;
    const __half* bP = Wb + (size_t)(n0blk + rb) * K;
    int sB0 = swoff(rb, cb), sB1 = swoff(rb, cb + 1);

    // ---- ldmatrix offsets ----
    int aoffs[TA][2], boffs[4][2];
    {
        int arr = warp_m * (BM/4) + (lane & 15);
        int achi = lane >> 4;
        #pragma unroll
        for (int t = 0; t < TA; ++t)
            #pragma unroll
            for (int ks = 0; ks < 2; ++ks)
                aoffs[t][ks] = swoff(arr + t * 16, ks * 2 + achi);
        int brr = warp_n * 64 + (lane & 7) + ((lane >> 4) << 3);
        int bchi = (lane >> 3) & 1;
        #pragma unroll
        for (int jj = 0; jj < 4; ++jj)
            #pragma unroll
            for (int ks = 0; ks < 2; ++ks)
                boffs[jj][ks] = swoff(brr + jj * 16, ks * 2 + bchi);
    }

    float acc[TA][8][4];
    #pragma unroll
    for (int t = 0; t < TA; ++t)
        #pragma unroll
        for (int j = 0; j < 8; ++j)
            #pragma unroll
            for (int q = 0; q < 4; ++q) acc[t][j][q] = 0.f;

    // stage c into buffer buf
    auto issue = [&](int c, int buf) {
        uint32_t sb = su + buf * STG;
        int k0 = c * 32;
        #pragma unroll
        for (int j = 0; j < CHT; ++j)
            CPA16(sb + sA[j], aP + k0 + (c0 + j) * 8, aSz);
        CPA16(sb + ABYTES + sB0, bP + k0 + cb * 8, 16u);
        CPA16(sb + ABYTES + sB1, bP + k0 + (cb + 1) * 8, 16u);
    };

    // prologue: 2 groups x 2 stages (buffers 0..3)
    issue(0, 0); issue(1, 1); CPCOMMIT();
    issue(2, 2); issue(3, 3); CPCOMMIT();

    for (int p = 0; p < NC/2; ++p) {
        CPWAIT(1);                 // stages 2p,2p+1 ready
        __syncthreads();
        int cs = 2*p + 4;
        int qb = ((p + 2) % 3) * 2;
        if (cs < NC) { issue(cs, qb); issue(cs + 1, qb + 1); }
        CPCOMMIT();                // exactly one group per iteration
        int pb = (p % 3) * 2;
        #pragma unroll
        for (int cc = 0; cc < 2; ++cc) {
            uint32_t base = su + (pb + cc) * STG;
            #pragma unroll
            for (int ks = 0; ks < 2; ++ks) {
                uint32_t Af[TA][4], Bf[8][2];
                #pragma unroll
                for (int t = 0; t < TA; ++t)
                    LDSM4(Af[t][0], Af[t][1], Af[t][2], Af[t][3], base + aoffs[t][ks]);
                #pragma unroll
                for (int jj = 0; jj < 4; ++jj)
                    LDSM4(Bf[2*jj][0], Bf[2*jj][1], Bf[2*jj+1][0], Bf[2*jj+1][1],
                          base + ABYTES + boffs[jj][ks]);
                #pragma unroll
                for (int t = 0; t < TA; ++t)
                    #pragma unroll
                    for (int j = 0; j < 8; ++j)
                        MMA16816(acc[t][j], Af[t], Bf[j]);
            }
        }
    }

    // ---- epilogue ----
    int mwarp = row0 + warp_m * (BM/4);
    #pragma unroll
    for (int t = 0; t < TA; ++t) {
        #pragma unroll
        for (int half = 0; half < 2; ++half) {
            int gr = mwarp + t * 16 + (lane >> 2) + half * 8;
            if (gr >= cnt) continue;
            float gate = 1.f;
            float* crowf = nullptr;
            __half* crh = nullptr;
            if (MODE == 0) crowf = Cout + (size_t)gr * O_;
            else {
                int p = lst[gr];
                if (MODE == 1) crh = g_Hh + (size_t)p * H_;
                else { crh = g_Yh + (size_t)p * H_; gate = g_gate[p]; }
            }
            #pragma unroll
            for (int j = 0; j < 8; ++j) {
                int n = n0blk + warp_n * 64 + j * 8 + (lane & 3) * 2;
                float v0 = acc[t][j][half*2 + 0] + bb[n];
                float v1 = acc[t][j][half*2 + 1] + bb[n + 1];
                if (MODE == 0) {
                    *reinterpret_cast<float2*>(crowf + n) = make_float2(v0, v1);
                } else {
                    if (MODE == 1) { v0 = fmaxf(v0, 0.f); v1 = fmaxf(v1, 0.f); }
                    else           { v0 *= gate; v1 *= gate; }
                    __half2 hv = __floats2half2_rn(v0, v1);
                    *reinterpret_cast<uint32_t*>(crh + n) = *reinterpret_cast<uint32_t*>(&hv);
                }
            }
        }
    }
}

// ---------------- combine: sum 4 fp16 pair rows, /S, to fp16 ----------------
#define H8 (H_/8)
__device__ __forceinline__ uint32_t comb4(uint32_t u0, uint32_t u1,
                                          uint32_t u2, uint32_t u3) {
    float2 f0 = __half22float2(*reinterpret_cast<__half2*>(&u0));
    float2 f1 = __half22float2(*reinterpret_cast<__half2*>(&u1));
    float2 f2 = __half22float2(*reinterpret_cast<__half2*>(&u2));
    float2 f3 = __half22float2(*reinterpret_cast<__half2*>(&u3));
    __half2 r = __floats2half2_rn(0.5f * (f0.x + f1.x + f2.x + f3.x),
                                  0.5f * (f0.y + f1.y + f2.y + f3.y));
    return *reinterpret_cast<uint32_t*>(&r);
}

__global__ void combine_kernel() {
    int idx = blockIdx.x * blockDim.x + threadIdx.x;   // B_ * H8
    int b  = idx >> 8;
    int gq = idx & (H8 - 1);
    const uint4* Y = reinterpret_cast<const uint4*>(g_Yh);
    size_t p0 = ((size_t)b * 2) * H8 + gq;            // s=0 pairs
    size_t p1 = ((size_t)(B_ + b) * 2) * H8 + gq;     // s=1 pairs
    uint4 a0 = Y[p0], a1 = Y[p0 + H8], a2 = Y[p1], a3 = Y[p1 + H8];
    uint4 r;
    r.x = comb4(a0.x, a1.x, a2.x, a3.x);
    r.y = comb4(a0.y, a1.y, a2.y, a3.y);
    r.z = comb4(a0.z, a1.z, a2.z, a3.z);
    r.w = comb4(a0.w, a1.w, a2.w, a3.w);
    reinterpret_cast<uint4*>(g_ch)[(size_t)b * H8 + gq] = r;
}

extern "C" void kernel_launch(void* const* d_in, const int* in_sizes, int n_in,
                              void* d_out, int out_size) {
    const float* xs      = (const float*)d_in[0];
    const float* Wg      = (const float*)d_in[1];
    const float* b       = (const float*)d_in[2];
    const float* fc1_w   = (const float*)d_in[3];
    const float* fc1_b   = (const float*)d_in[4];
    const float* fc2_w   = (const float*)d_in[5];
    const float* fc2_b   = (const float*)d_in[6];
    const float* final_w = (const float*)d_in[7];
    const float* final_b = (const float*)d_in[8];
    float* out = (float*)d_out;

    constexpr int SMEM12 = NSTG * (128*64 + 128*64);  // 96 KB
    constexpr int SMEM0  = NSTG * ( 64*64 + 128*64);  // 72 KB
    cudaFuncSetAttribute(mma_gemm<0>, cudaFuncAttributeMaxDynamicSharedMemorySize, SMEM0);
    cudaFuncSetAttribute(mma_gemm<1>, cudaFuncAttributeMaxDynamicSharedMemorySize, SMEM12);
    cudaFuncSetAttribute(mma_gemm<2>, cudaFuncAttributeMaxDynamicSharedMemorySize, SMEM12);

    int* cnt_ptr = nullptr;
    cudaGetSymbolAddress((void**)&cnt_ptr, g_cnt);
    cudaMemsetAsync(cnt_ptr, 0, sizeof(int) * E_, 0);

    gating_kernel<<<T_/16, 256>>>(xs, Wg, b, out);
    pack_all<<<PACK_BLKS, 256>>>(xs, fc1_w, fc2_w, final_w);

    dim3 g1(H_/128, MAXR/128, E_);
    mma_gemm<1><<<g1, 256, SMEM12>>>(fc1_b, nullptr);
    mma_gemm<2><<<g1, 256, SMEM12>>>(fc2_b, nullptr);
    combine_kernel<<<(B_*H8)/256, 256>>>();
    dim3 gf(O_/128, B_/64);
    mma_gemm<0><<<gf, 256, SMEM0>>>(final_b, out);
}

// round 17
// speedup vs baseline: 1.0565x; 1.0565x over previous
#include <cuda_runtime.h>
#include <cuda_bf16.h>
#include <cuda_fp16.h>
#include <math.h>
#include <stdint.h>

// Problem constants
#define S_ 2
#define B_ 2048
#define D_ 1024
#define H_ 2048
#define E_ 8
#define O_ 1024
#define T_ (S_*B_)        // 4096 tokens
#define P_ (T_*2)         // 8192 (token, k) pairs
#define MAXR 4096
#define OUT_OFF ((size_t)B_*O_)

// ---------------- scratch (device globals) ----------------
__device__ __align__(128) __half g_xh[(size_t)T_ * D_];
__device__ __align__(128) __half g_w1h[(size_t)E_ * H_ * D_];
__device__ __align__(128) __half g_w2h[(size_t)E_ * H_ * H_];
__device__ __align__(128) __half g_fwh[(size_t)O_ * H_];
__device__ __align__(128) __half g_Hh[(size_t)P_ * H_];
__device__ __align__(128) __half g_Yh[(size_t)P_ * H_];
__device__ __align__(128) __half g_ch[(size_t)B_ * H_];
__device__ __align__(128) float g_gate[P_];
__device__ __align__(128) int   g_list[E_ * MAXR];
__device__ int   g_cnt[E_];

__device__ __forceinline__ uint32_t smem_u32(const void* p) {
    uint32_t a;
    asm("{ .reg .u64 t; cvta.to.shared.u64 t, %1; cvt.u32.u64 %0, t; }" : "=r"(a) : "l"(p));
    return a;
}

#define LDSM4(r0, r1, r2, r3, addr) \
    asm volatile("ldmatrix.sync.aligned.m8n8.x4.shared.b16 {%0,%1,%2,%3}, [%4];" \
        : "=r"(r0), "=r"(r1), "=r"(r2), "=r"(r3) : "r"(addr))

#define MMA16816(d, a, b) \
    asm volatile("mma.sync.aligned.m16n8k16.row.col.f32.f16.f16.f32 " \
        "{%0,%1,%2,%3}, {%4,%5,%6,%7}, {%8,%9}, {%0,%1,%2,%3};" \
        : "+f"((d)[0]), "+f"((d)[1]), "+f"((d)[2]), "+f"((d)[3]) \
        : "r"((a)[0]), "r"((a)[1]), "r"((a)[2]), "r"((a)[3]), \
          "r"((b)[0]), "r"((b)[1]))

#define CPA16(dst, src, sz) \
    asm volatile("cp.async.cg.shared.global [%0], [%1], 16, %2;" \
        :: "r"(dst), "l"(src), "r"(sz) : "memory")
#define CPCOMMIT() asm volatile("cp.async.commit_group;" ::: "memory")
#define CPWAIT(n)  asm volatile("cp.async.wait_group %0;" :: "n"(n) : "memory")

// swizzled byte offset within an N-row x 32-col fp16 plane (64B rows, 4x16B chunks)
__device__ __forceinline__ int swoff(int r, int c) {
    return r * 64 + ((c ^ ((r >> 1) & 3)) << 4);
}

// ---------------- fused pack: xs|w1|w2|fw -> fp16 ----------------
#define XSF4 (T_*D_/4)      // 1048576
#define W1F4 (E_*H_*D_/4)   // 4194304
#define W2F4 (E_*H_*H_/4)   // 8388608
#define FWF4 (O_*H_/4)      // 524288
#define PACK_BLKS 3552

__device__ __forceinline__ void pack_loop(const float* __restrict__ s,
                                          __half* __restrict__ d,
                                          size_t n4, size_t i0, size_t stride) {
    for (size_t j = i0; j < n4; j += stride) {
        float4 v = reinterpret_cast<const float4*>(s)[j];
        __half2 a = __floats2half2_rn(v.x, v.y);
        __half2 b = __floats2half2_rn(v.z, v.w);
        uint2 o;
        o.x = *reinterpret_cast<uint32_t*>(&a);
        o.y = *reinterpret_cast<uint32_t*>(&b);
        reinterpret_cast<uint2*>(d)[j] = o;
    }
}

__global__ __launch_bounds__(256) void pack_all(
        const float* __restrict__ xs, const float* __restrict__ w1,
        const float* __restrict__ w2, const float* __restrict__ fw)
{
    size_t i0 = (size_t)blockIdx.x * 256 + threadIdx.x;
    size_t stride = (size_t)PACK_BLKS * 256;
    pack_loop(xs, g_xh,  XSF4, i0, stride);
    pack_loop(w1, g_w1h, W1F4, i0, stride);
    pack_loop(w2, g_w2h, W2F4, i0, stride);
    pack_loop(fw, g_fwh, FWF4, i0, stride);
}

// ---------------- gating: 256 blocks x 16 tokens ----------------
__global__ __launch_bounds__(256) void gating_kernel(
        const float* __restrict__ xs, const float* __restrict__ Wg,
        const float* __restrict__ bias, float* __restrict__ out)
{
    __shared__ __align__(16) float ws[E_][D_];
    int tid = threadIdx.x;
    for (int i = tid; i < E_*D_; i += 256) {
        int e = i >> 10, d = i & (D_-1);
        ws[e][d] = Wg[d*E_ + e];
    }
    __syncthreads();
    int warp = tid >> 5, lane = tid & 31;
    for (int tt = 0; tt < 2; ++tt) {
        int t = blockIdx.x * 16 + warp * 2 + tt;
        float acc[E_];
        #pragma unroll
        for (int e = 0; e < E_; ++e) acc[e] = 0.f;
        const float4* xrow = reinterpret_cast<const float4*>(xs + (size_t)t * D_);
        #pragma unroll
        for (int it = 0; it < D_/128; ++it) {
            float4 x = xrow[lane + it*32];
            #pragma unroll
            for (int e = 0; e < E_; ++e) {
                float4 w = reinterpret_cast<const float4*>(ws[e])[lane + it*32];
                acc[e] += x.x*w.x + x.y*w.y + x.z*w.z + x.w*w.w;
            }
        }
        #pragma unroll
        for (int off = 16; off > 0; off >>= 1) {
            #pragma unroll
            for (int e = 0; e < E_; ++e)
                acc[e] += __shfl_xor_sync(0xffffffffu, acc[e], off);
        }
        if (lane == 0) {
            float h[E_];
            #pragma unroll
            for (int e = 0; e < E_; ++e) h[e] = acc[e] + bias[e];
            float m1 = h[0]; int i1 = 0;
            #pragma unroll
            for (int e = 1; e < E_; ++e) if (h[e] > m1) { m1 = h[e]; i1 = e; }
            float m2 = -3.0e38f; int i2 = 0;
            #pragma unroll
            for (int e = 0; e < E_; ++e) if (e != i1 && h[e] > m2) { m2 = h[e]; i2 = e; }
            float pr[E_]; float den = 0.f;
            #pragma unroll
            for (int e = 0; e < E_; ++e) { pr[e] = expf(h[e] - m1); den += pr[e]; }
            float inv = 1.f / den;
            float* ep = out + OUT_OFF + (size_t)t * E_;
            #pragma unroll
            for (int e = 0; e < E_; ++e) ep[e] = pr[e] * inv;
            float l2 = expf(m2 - m1);
            float gd = 1.f + l2;
            g_gate[t*2]     = 1.f / gd;
            g_gate[t*2 + 1] = l2 / gd;
            int pos = atomicAdd(&g_cnt[i1], 1); g_list[i1*MAXR + pos] = t*2;
            pos     = atomicAdd(&g_cnt[i2], 1); g_list[i2*MAXR + pos] = t*2 + 1;
        }
    }
}

// ---- fp16 mma.sync GEMM: 256 threads, tile BMx128, BK=32, 6-stage, 2 CTA/SM ----
// (round-14 loop structure exactly; fp16 outputs for fc1/fc2)
// Warp grid: 4 (m) x 2 (n); warp tile (BM/4) x 64.
// MODE 0: final (A=g_ch, W=g_fwh, C=out,  K=2048, N=1024, BM=64)
// MODE 1: fc1   (A=g_xh by token, W=g_w1h, C=g_Hh fp16, K=1024, N=2048, relu, BM=128)
// MODE 2: fc2   (A=g_Hh by pair,  W=g_w2h, C=g_Yh fp16, K=2048, N=2048, *gate, BM=128)
#define NSTG 6

template<int MODE>
__global__ __launch_bounds__(256, 2) void mma_gemm(
        const float* __restrict__ biasF, float* __restrict__ Cout)
{
    constexpr int K    = (MODE == 1) ? 1024 : 2048;
    constexpr int NTOT = (MODE == 0) ? 1024 : 2048;
    constexpr int NC   = K / 32;
    constexpr int BM   = (MODE == 0) ? 64 : 128;
    constexpr int TA   = BM / 64;            // m16 tiles per warp: 1 or 2
    constexpr int TPR  = 256 / BM;           // threads per A row: 4 or 2
    constexpr int CHT  = 4 / TPR;            // A chunks per thread: 1 or 2
    constexpr int ABYTES = BM * 64;
    constexpr int STG  = ABYTES + 128 * 64;

    const __half *Ah_g, *Wh_g;
    if (MODE == 0)      { Ah_g = g_ch;  Wh_g = g_fwh; }
    else if (MODE == 1) { Ah_g = g_xh;  Wh_g = g_w1h; }
    else                { Ah_g = g_Hh;  Wh_g = g_w2h; }

    int e = (MODE == 0) ? 0 : blockIdx.z;
    int cnt;
    const int* lst = nullptr;
    if (MODE == 0) cnt = B_;
    else { cnt = g_cnt[e]; lst = g_list + e * MAXR; }
    int row0 = blockIdx.y * BM;
    if (row0 >= cnt) return;
    int n0blk = blockIdx.x * 128;
    const __half* Wb = Wh_g + (size_t)e * NTOT * K;
    const float* bb = biasF + (size_t)e * ((MODE == 0) ? 0 : NTOT);

    extern __shared__ unsigned char sm[];
    uint32_t su = smem_u32(sm);

    int tid = threadIdx.x;
    int wid = tid >> 5, lane = tid & 31;
    int warp_m = wid >> 1;        // 0..3 (BM/4 rows each)
    int warp_n = wid & 1;         // 0..1 (64 cols each)

    // ---- cp.async assignment ----
    int r_ld = tid / TPR;                 // 0..BM-1
    int c0   = (tid % TPR) * CHT;         // starting chunk
    int gr_ld = row0 + r_ld;
    uint32_t aSz = (gr_ld < cnt) ? 16u : 0u;
    int aridx;
    if (MODE == 0) aridx = (gr_ld < cnt) ? gr_ld : 0;
    else {
        int p = (gr_ld < cnt) ? lst[gr_ld] : 0;
        aridx = (MODE == 1) ? (p >> 1) : p;
    }
    const __half* aP = Ah_g + (size_t)aridx * K;
    int sA[CHT];
    #pragma unroll
    for (int j = 0; j < CHT; ++j) sA[j] = swoff(r_ld, c0 + j);
    // B: 128 rows x 4 chunks; thread tid>>1 handles row, 2 chunks at (tid&1)*2
    int rb = tid >> 1, cb = (tid & 1) * 2;
    const __half* bP = Wb + (size_t)(n0blk + rb) * K;
    int sB0 = swoff(rb, cb), sB1 = swoff(rb, cb + 1);

    // ---- ldmatrix offsets ----
    int aoffs[TA][2], boffs[4][2];
    {
        int arr = warp_m * (BM/4) + (lane & 15);
        int achi = lane >> 4;
        #pragma unroll
        for (int t = 0; t < TA; ++t)
            #pragma unroll
            for (int ks = 0; ks < 2; ++ks)
                aoffs[t][ks] = swoff(arr + t * 16, ks * 2 + achi);
        int brr = warp_n * 64 + (lane & 7) + ((lane >> 4) << 3);
        int bchi = (lane >> 3) & 1;
        #pragma unroll
        for (int jj = 0; jj < 4; ++jj)
            #pragma unroll
            for (int ks = 0; ks < 2; ++ks)
                boffs[jj][ks] = swoff(brr + jj * 16, ks * 2 + bchi);
    }

    float acc[TA][8][4];
    #pragma unroll
    for (int t = 0; t < TA; ++t)
        #pragma unroll
        for (int j = 0; j < 8; ++j)
            #pragma unroll
            for (int q = 0; q < 4; ++q) acc[t][j][q] = 0.f;

    auto issue = [&](int c) {
        uint32_t sb = su + (c % NSTG) * STG;
        int k0 = c * 32;
        #pragma unroll
        for (int j = 0; j < CHT; ++j)
            CPA16(sb + sA[j], aP + k0 + (c0 + j) * 8, aSz);
        CPA16(sb + ABYTES + sB0, bP + k0 + cb * 8, 16u);
        CPA16(sb + ABYTES + sB1, bP + k0 + (cb + 1) * 8, 16u);
    };

    #pragma unroll
    for (int c = 0; c < NSTG - 1; ++c) { issue(c); CPCOMMIT(); }

    for (int c = 0; c < NC; ++c) {
        CPWAIT(NSTG - 2);
        __syncthreads();
        // exactly one commit per iteration (possibly empty near tail)
        if (c + NSTG - 1 < NC) issue(c + NSTG - 1);
        CPCOMMIT();
        uint32_t base = su + (c % NSTG) * STG;
        #pragma unroll
        for (int ks = 0; ks < 2; ++ks) {
            uint32_t Af[TA][4], Bf[8][2];
            #pragma unroll
            for (int t = 0; t < TA; ++t)
                LDSM4(Af[t][0], Af[t][1], Af[t][2], Af[t][3], base + aoffs[t][ks]);
            #pragma unroll
            for (int jj = 0; jj < 4; ++jj)
                LDSM4(Bf[2*jj][0], Bf[2*jj][1], Bf[2*jj+1][0], Bf[2*jj+1][1],
                      base + ABYTES + boffs[jj][ks]);
            #pragma unroll
            for (int t = 0; t < TA; ++t)
                #pragma unroll
                for (int j = 0; j < 8; ++j)
                    MMA16816(acc[t][j], Af[t], Bf[j]);
        }
    }

    // ---- epilogue ----
    int mwarp = row0 + warp_m * (BM/4);
    #pragma unroll
    for (int t = 0; t < TA; ++t) {
        #pragma unroll
        for (int half = 0; half < 2; ++half) {
            int gr = mwarp + t * 16 + (lane >> 2) + half * 8;
            if (gr >= cnt) continue;
            float gate = 1.f;
            float* crowf = nullptr;
            __half* crh = nullptr;
            if (MODE == 0) crowf = Cout + (size_t)gr * O_;
            else {
                int p = lst[gr];
                if (MODE == 1) crh = g_Hh + (size_t)p * H_;
                else { crh = g_Yh + (size_t)p * H_; gate = g_gate[p]; }
            }
            #pragma unroll
            for (int j = 0; j < 8; ++j) {
                int n = n0blk + warp_n * 64 + j * 8 + (lane & 3) * 2;
                float v0 = acc[t][j][half*2 + 0] + bb[n];
                float v1 = acc[t][j][half*2 + 1] + bb[n + 1];
                if (MODE == 0) {
                    *reinterpret_cast<float2*>(crowf + n) = make_float2(v0, v1);
                } else {
                    if (MODE == 1) { v0 = fmaxf(v0, 0.f); v1 = fmaxf(v1, 0.f); }
                    else           { v0 *= gate; v1 *= gate; }
                    __half2 hv = __floats2half2_rn(v0, v1);
                    *reinterpret_cast<uint32_t*>(crh + n) = *reinterpret_cast<uint32_t*>(&hv);
                }
            }
        }
    }
}

// ---------------- combine: sum 4 fp16 pair rows, /S, to fp16 ----------------
#define H8 (H_/8)
__device__ __forceinline__ uint32_t comb4(uint32_t u0, uint32_t u1,
                                          uint32_t u2, uint32_t u3) {
    float2 f0 = __half22float2(*reinterpret_cast<__half2*>(&u0));
    float2 f1 = __half22float2(*reinterpret_cast<__half2*>(&u1));
    float2 f2 = __half22float2(*reinterpret_cast<__half2*>(&u2));
    float2 f3 = __half22float2(*reinterpret_cast<__half2*>(&u3));
    __half2 r = __floats2half2_rn(0.5f * (f0.x + f1.x + f2.x + f3.x),
                                  0.5f * (f0.y + f1.y + f2.y + f3.y));
    return *reinterpret_cast<uint32_t*>(&r);
}

__global__ void combine_kernel() {
    int idx = blockIdx.x * blockDim.x + threadIdx.x;   // B_ * H8
    int b  = idx >> 8;
    int gq = idx & (H8 - 1);
    const uint4* Y = reinterpret_cast<const uint4*>(g_Yh);
    size_t p0 = ((size_t)b * 2) * H8 + gq;            // s=0 pairs
    size_t p1 = ((size_t)(B_ + b) * 2) * H8 + gq;     // s=1 pairs
    uint4 a0 = Y[p0], a1 = Y[p0 + H8], a2 = Y[p1], a3 = Y[p1 + H8];
    uint4 r;
    r.x = comb4(a0.x, a1.x, a2.x, a3.x);
    r.y = comb4(a0.y, a1.y, a2.y, a3.y);
    r.z = comb4(a0.z, a1.z, a2.z, a3.z);
    r.w = comb4(a0.w, a1.w, a2.w, a3.w);
    reinterpret_cast<uint4*>(g_ch)[(size_t)b * H8 + gq] = r;
}

extern "C" void kernel_launch(void* const* d_in, const int* in_sizes, int n_in,
                              void* d_out, int out_size) {
    const float* xs      = (const float*)d_in[0];
    const float* Wg      = (const float*)d_in[1];
    const float* b       = (const float*)d_in[2];
    const float* fc1_w   = (const float*)d_in[3];
    const float* fc1_b   = (const float*)d_in[4];
    const float* fc2_w   = (const float*)d_in[5];
    const float* fc2_b   = (const float*)d_in[6];
    const float* final_w = (const float*)d_in[7];
    const float* final_b = (const float*)d_in[8];
    float* out = (float*)d_out;

    constexpr int SMEM12 = NSTG * (128*64 + 128*64);  // 96 KB
    constexpr int SMEM0  = NSTG * ( 64*64 + 128*64);  // 72 KB
    cudaFuncSetAttribute(mma_gemm<0>, cudaFuncAttributeMaxDynamicSharedMemorySize, SMEM0);
    cudaFuncSetAttribute(mma_gemm<1>, cudaFuncAttributeMaxDynamicSharedMemorySize, SMEM12);
    cudaFuncSetAttribute(mma_gemm<2>, cudaFuncAttributeMaxDynamicSharedMemorySize, SMEM12);

    int* cnt_ptr = nullptr;
    cudaGetSymbolAddress((void**)&cnt_ptr, g_cnt);
    cudaMemsetAsync(cnt_ptr, 0, sizeof(int) * E_, 0);

    gating_kernel<<<T_/16, 256>>>(xs, Wg, b, out);
    pack_all<<<PACK_BLKS, 256>>>(xs, fc1_w, fc2_w, final_w);

    dim3 g1(H_/128, MAXR/128, E_);
    mma_gemm<1><<<g1, 256, SMEM12>>>(fc1_b, nullptr);
    mma_gemm<2><<<g1, 256, SMEM12>>>(fc2_b, nullptr);
    combine_kernel<<<(B_*H8)/256, 256>>>();
    dim3 gf(O_/128, B_/64);
    mma_gemm<0><<<gf, 256, SMEM0>>>(final_b, out);
}